// round 1
// baseline (speedup 1.0000x reference)
#include <cuda_runtime.h>
#include <math.h>

#define N 8192
#define D 256
#define LAMF 10.0f
#define INV_LAM 0.1f
// -LAM * log(N) = -10 * 13 * ln(2)
#define NEG_LAM_LOGN (-90.109133472792885f)
#define NCHUNK 16
#define ROWS_PER_CHUNK (N / NCHUNK)   // 512

// ---- scratch (static device globals; no allocation allowed) ----
__device__ float g_C[(size_t)N * N];      // 256 MB cost matrix
__device__ float g_f[N];
__device__ float g_g[N];
__device__ float g_x2[N];
__device__ float g_y2[N];
__device__ float g_pm[NCHUNK * N];
__device__ float g_ps[NCHUNK * N];
__device__ float g_cost[N];

// ---- online logsumexp helpers (branchless) ----
__device__ __forceinline__ void lse_acc(float& m, float& s, float v) {
    float mn = fmaxf(m, v);
    s = s * __expf(m - mn) + __expf(v - mn);
    m = mn;
}
__device__ __forceinline__ void lse_merge(float& M, float& S, float m2, float s2) {
    float mn = fmaxf(M, m2);
    S = S * __expf(M - mn) + s2 * __expf(m2 - mn);
    M = mn;
}

// ============================================================
// 1) row norms of X and Y
// ============================================================
__global__ __launch_bounds__(256) void norms_kernel(const float* __restrict__ X,
                                                    const float* __restrict__ Y) {
    int r = blockIdx.x;
    const float* src = (r < N) ? (X + (size_t)r * D) : (Y + (size_t)(r - N) * D);
    float v = src[threadIdx.x];
    v *= v;
    __shared__ float sh[256];
    sh[threadIdx.x] = v;
    __syncthreads();
    for (int off = 128; off > 0; off >>= 1) {
        if (threadIdx.x < off) sh[threadIdx.x] += sh[threadIdx.x + off];
        __syncthreads();
    }
    if (threadIdx.x == 0) {
        if (r < N) g_x2[r] = sh[0];
        else       g_y2[r - N] = sh[0];
    }
}

// ============================================================
// 2) C = sqrt(max(x2 + y2 - 2 X Y^T, 0) + 1e-6), tiled fp32 GEMM
//    64x64 tile, BK=32, 256 threads, 4x4 per thread
// ============================================================
#define BM 64
#define BN 64
#define BK 32

__global__ __launch_bounds__(256) void cost_gemm(const float* __restrict__ X,
                                                 const float* __restrict__ Y) {
    __shared__ float Xs[BK][BM + 4];
    __shared__ float Ys[BK][BN + 4];

    const int bm = blockIdx.y * BM;
    const int bn = blockIdx.x * BN;
    const int tid = threadIdx.x;
    const int tx = tid & 15;        // 0..15 -> N dim
    const int ty = tid >> 4;        // 0..15 -> M dim

    const int lr = tid >> 3;        // 0..31 row within half-tile
    const int lk = (tid & 7) * 4;   // K offset (float4)

    float acc[4][4];
#pragma unroll
    for (int i = 0; i < 4; i++)
#pragma unroll
        for (int j = 0; j < 4; j++) acc[i][j] = 0.0f;

    for (int k0 = 0; k0 < D; k0 += BK) {
#pragma unroll
        for (int h = 0; h < 2; h++) {
            int row = lr + h * 32;
            float4 v = *(const float4*)&X[(size_t)(bm + row) * D + k0 + lk];
            Xs[lk + 0][row] = v.x; Xs[lk + 1][row] = v.y;
            Xs[lk + 2][row] = v.z; Xs[lk + 3][row] = v.w;
            float4 w = *(const float4*)&Y[(size_t)(bn + row) * D + k0 + lk];
            Ys[lk + 0][row] = w.x; Ys[lk + 1][row] = w.y;
            Ys[lk + 2][row] = w.z; Ys[lk + 3][row] = w.w;
        }
        __syncthreads();

#pragma unroll
        for (int k = 0; k < BK; k++) {
            float a[4], b[4];
#pragma unroll
            for (int i = 0; i < 4; i++) a[i] = Xs[k][ty * 4 + i];
#pragma unroll
            for (int j = 0; j < 4; j++) b[j] = Ys[k][tx * 4 + j];
#pragma unroll
            for (int i = 0; i < 4; i++)
#pragma unroll
                for (int j = 0; j < 4; j++) acc[i][j] = fmaf(a[i], b[j], acc[i][j]);
        }
        __syncthreads();
    }

#pragma unroll
    for (int i = 0; i < 4; i++) {
        int row = bm + ty * 4 + i;
        float x2 = g_x2[row];
#pragma unroll
        for (int j = 0; j < 4; j++) {
            int col = bn + tx * 4 + j;
            float sq = x2 + g_y2[col] - 2.0f * acc[i][j];
            g_C[(size_t)row * N + col] = sqrtf(fmaxf(sq, 0.0f) + 1e-6f);
        }
    }
}

// ============================================================
// 3) init g = 0
// ============================================================
__global__ void init_g() {
    g_g[blockIdx.x * 256 + threadIdx.x] = 0.0f;
}

// ============================================================
// 4) row pass: f_i = -LAM*log(N) - LAM * LSE_j((g_j - C_ij)/LAM)
//    one block per row, 256 threads, 4 independent online-LSE chains
// ============================================================
__global__ __launch_bounds__(256) void row_pass() {
    const int i = blockIdx.x;
    const int tid = threadIdx.x;
    const float* __restrict__ Crow = g_C + (size_t)i * N;

    float m[4] = {-INFINITY, -INFINITY, -INFINITY, -INFINITY};
    float s[4] = {0.0f, 0.0f, 0.0f, 0.0f};

#pragma unroll
    for (int k = 0; k < N / 256; k++) {
        int j = tid + k * 256;
        float v = (__ldg(&g_g[j]) - __ldg(&Crow[j])) * INV_LAM;
        int c = k & 3;
        lse_acc(m[c], s[c], v);
    }
    float M = m[0], S = s[0];
    lse_merge(M, S, m[1], s[1]);
    lse_merge(M, S, m[2], s[2]);
    lse_merge(M, S, m[3], s[3]);

    __shared__ float sm[256], ss[256];
    sm[tid] = M; ss[tid] = S;
    __syncthreads();
    for (int off = 128; off > 0; off >>= 1) {
        if (tid < off) {
            float Ma = sm[tid], Sa = ss[tid];
            lse_merge(Ma, Sa, sm[tid + off], ss[tid + off]);
            sm[tid] = Ma; ss[tid] = Sa;
        }
        __syncthreads();
    }
    if (tid == 0) g_f[i] = NEG_LAM_LOGN - LAMF * (sm[0] + logf(ss[0]));
}

// ============================================================
// 5) column pass (partial): per-chunk online LSE over rows, per column
//    grid (N/256, NCHUNK); thread handles one column, 512 rows,
//    8 independent chains; reads of C are row-major coalesced.
// ============================================================
__global__ __launch_bounds__(256) void col_pass_partial() {
    const int j = blockIdx.x * 256 + threadIdx.x;
    const int i0 = blockIdx.y * ROWS_PER_CHUNK;

    __shared__ float sf[ROWS_PER_CHUNK];
    for (int r = threadIdx.x; r < ROWS_PER_CHUNK; r += 256) sf[r] = g_f[i0 + r];
    __syncthreads();

    const float* __restrict__ Ccol = g_C + (size_t)i0 * N + j;

    float m[8], s[8];
#pragma unroll
    for (int c = 0; c < 8; c++) { m[c] = -INFINITY; s[c] = 0.0f; }

#pragma unroll 8
    for (int r = 0; r < ROWS_PER_CHUNK; r++) {
        float v = (sf[r] - __ldg(&Ccol[(size_t)r * N])) * INV_LAM;
        int c = r & 7;
        lse_acc(m[c], s[c], v);
    }
    float M = m[0], S = s[0];
#pragma unroll
    for (int c = 1; c < 8; c++) lse_merge(M, S, m[c], s[c]);

    g_pm[blockIdx.y * N + j] = M;
    g_ps[blockIdx.y * N + j] = S;
}

// ============================================================
// 6) column pass combine: g_j from NCHUNK partials
// ============================================================
__global__ __launch_bounds__(256) void col_combine() {
    const int j = blockIdx.x * 256 + threadIdx.x;
    float M = -INFINITY, S = 0.0f;
#pragma unroll
    for (int c = 0; c < NCHUNK; c++) {
        lse_merge(M, S, g_pm[c * N + j], g_ps[c * N + j]);
    }
    g_g[j] = NEG_LAM_LOGN - LAMF * (M + logf(S));
}

// ============================================================
// 7) final: pi = exp((f_i + g_j - C)/LAM), per-row cost partials
// ============================================================
__global__ __launch_bounds__(256) void pi_cost(float* __restrict__ out) {
    const int i = blockIdx.x;
    const int tid = threadIdx.x;
    const float fi = g_f[i];
    const float* __restrict__ Crow = g_C + (size_t)i * N;
    float* __restrict__ orow = out + 1 + (size_t)i * N;

    float acc = 0.0f;
#pragma unroll
    for (int k = 0; k < N / 256; k++) {
        int j = tid + k * 256;
        float C = __ldg(&Crow[j]);
        float p = __expf((fi + __ldg(&g_g[j]) - C) * INV_LAM);
        orow[j] = p;
        acc = fmaf(p, C, acc);
    }
    __shared__ float sh[256];
    sh[tid] = acc;
    __syncthreads();
    for (int off = 128; off > 0; off >>= 1) {
        if (tid < off) sh[tid] += sh[tid + off];
        __syncthreads();
    }
    if (tid == 0) g_cost[i] = sh[0];
}

// ============================================================
// 8) deterministic final cost reduction (single block)
// ============================================================
__global__ __launch_bounds__(1024) void cost_reduce(float* __restrict__ out) {
    __shared__ float sh[1024];
    float a = 0.0f;
    for (int k = threadIdx.x; k < N; k += 1024) a += g_cost[k];
    sh[threadIdx.x] = a;
    __syncthreads();
    for (int off = 512; off > 0; off >>= 1) {
        if (threadIdx.x < off) sh[threadIdx.x] += sh[threadIdx.x + off];
        __syncthreads();
    }
    if (threadIdx.x == 0) out[0] = sh[0];
}

// ============================================================
extern "C" void kernel_launch(void* const* d_in, const int* in_sizes, int n_in,
                              void* d_out, int out_size) {
    const float* X = (const float*)d_in[0];
    const float* Y = (const float*)d_in[1];
    float* out = (float*)d_out;

    norms_kernel<<<2 * N, 256>>>(X, Y);
    dim3 ggrid(N / BN, N / BM);
    cost_gemm<<<ggrid, 256>>>(X, Y);
    init_g<<<N / 256, 256>>>();

    for (int it = 0; it < 50; it++) {
        row_pass<<<N, 256>>>();
        col_pass_partial<<<dim3(N / 256, NCHUNK), 256>>>();
        col_combine<<<N / 256, 256>>>();
    }

    pi_cost<<<N, 256>>>(out);
    cost_reduce<<<1, 1024>>>(out);
}

// round 3
// speedup vs baseline: 2.1627x; 2.1627x over previous
#include <cuda_runtime.h>
#include <cuda_fp16.h>
#include <math.h>

#define N 8192
#define D 256
#define LAMF 10.0f
#define INV_LAM 0.1f
#define NEG_LAM_LOGN (-90.109133472792885f)

#define CCHUNK 64
#define CROWS (N / CCHUNK)        // 128 rows per column-chunk
#define ROWS_PER_BLK 8            // rows per block in row pass

// ---- scratch (static device globals; no allocation allowed) ----
__device__ float  g_C[(size_t)N * N];   // fp32 cost matrix (final pass only)
__device__ __half g_E[(size_t)N * N];   // exp(-C/lam) fp16 (iteration passes)
__device__ float  g_f[N];
__device__ float  g_g[N];
__device__ float  g_Ef[N];              // exp(f/lam)
__device__ float  g_Eg[N];              // exp(g/lam)
__device__ float  g_x2[N];
__device__ float  g_y2[N];
__device__ float  g_part[(size_t)CCHUNK * N];
__device__ float  g_cost[N];

// ============================================================
// 1) row norms of X and Y
// ============================================================
__global__ __launch_bounds__(256) void norms_kernel(const float* __restrict__ X,
                                                    const float* __restrict__ Y) {
    int r = blockIdx.x;
    const float* src = (r < N) ? (X + (size_t)r * D) : (Y + (size_t)(r - N) * D);
    float v = src[threadIdx.x];
    v *= v;
    __shared__ float sh[256];
    sh[threadIdx.x] = v;
    __syncthreads();
    for (int off = 128; off > 0; off >>= 1) {
        if (threadIdx.x < off) sh[threadIdx.x] += sh[threadIdx.x + off];
        __syncthreads();
    }
    if (threadIdx.x == 0) {
        if (r < N) g_x2[r] = sh[0];
        else       g_y2[r - N] = sh[0];
    }
}

// ============================================================
// 2) GEMM: C = sqrt(max(x2+y2-2XY^T,0)+1e-6), also E = exp(-C/lam) fp16
//    128x128 tile, BK=16, 256 threads, 8x8 per thread
// ============================================================
#define GBM 128
#define GBN 128
#define GBK 16

__global__ __launch_bounds__(256) void cost_gemm(const float* __restrict__ X,
                                                 const float* __restrict__ Y) {
    __shared__ float Xs[GBK][GBM + 4];
    __shared__ float Ys[GBK][GBN + 4];

    const int tid = threadIdx.x;
    const int bm = blockIdx.y * GBM;
    const int bn = blockIdx.x * GBN;
    const int tx = tid & 15;       // 0..15 -> N dim (8 cols each)
    const int ty = tid >> 4;       // 0..15 -> M dim (8 rows each)
    const int lr = tid >> 2;       // 0..63
    const int lk = (tid & 3) * 4;  // 0,4,8,12

    float acc[8][8];
#pragma unroll
    for (int i = 0; i < 8; i++)
#pragma unroll
        for (int j = 0; j < 8; j++) acc[i][j] = 0.0f;

    for (int k0 = 0; k0 < D; k0 += GBK) {
#pragma unroll
        for (int h = 0; h < 2; h++) {
            int row = lr + h * 64;
            float4 v = *(const float4*)&X[(size_t)(bm + row) * D + k0 + lk];
            Xs[lk + 0][row] = v.x; Xs[lk + 1][row] = v.y;
            Xs[lk + 2][row] = v.z; Xs[lk + 3][row] = v.w;
            float4 w = *(const float4*)&Y[(size_t)(bn + row) * D + k0 + lk];
            Ys[lk + 0][row] = w.x; Ys[lk + 1][row] = w.y;
            Ys[lk + 2][row] = w.z; Ys[lk + 3][row] = w.w;
        }
        __syncthreads();

#pragma unroll
        for (int k = 0; k < GBK; k++) {
            float a[8], b[8];
            *(float4*)&a[0] = *(const float4*)&Xs[k][ty * 8];
            *(float4*)&a[4] = *(const float4*)&Xs[k][ty * 8 + 4];
            *(float4*)&b[0] = *(const float4*)&Ys[k][tx * 8];
            *(float4*)&b[4] = *(const float4*)&Ys[k][tx * 8 + 4];
#pragma unroll
            for (int i = 0; i < 8; i++)
#pragma unroll
                for (int j = 0; j < 8; j++) acc[i][j] = fmaf(a[i], b[j], acc[i][j]);
        }
        __syncthreads();
    }

    float x2[8], y2[8];
#pragma unroll
    for (int i = 0; i < 8; i++) x2[i] = g_x2[bm + ty * 8 + i];
#pragma unroll
    for (int j = 0; j < 8; j++) y2[j] = g_y2[bn + tx * 8 + j];

#pragma unroll
    for (int i = 0; i < 8; i++) {
        size_t row = (size_t)(bm + ty * 8 + i);
        float c[8];
#pragma unroll
        for (int j = 0; j < 8; j++) {
            float sq = x2[i] + y2[j] - 2.0f * acc[i][j];
            c[j] = sqrtf(fmaxf(sq, 0.0f) + 1e-6f);
        }
        float* crow = g_C + row * N + bn + tx * 8;
        *(float4*)&crow[0] = make_float4(c[0], c[1], c[2], c[3]);
        *(float4*)&crow[4] = make_float4(c[4], c[5], c[6], c[7]);

        __half2 h0 = __floats2half2_rn(__expf(-c[0] * INV_LAM), __expf(-c[1] * INV_LAM));
        __half2 h1 = __floats2half2_rn(__expf(-c[2] * INV_LAM), __expf(-c[3] * INV_LAM));
        __half2 h2 = __floats2half2_rn(__expf(-c[4] * INV_LAM), __expf(-c[5] * INV_LAM));
        __half2 h3 = __floats2half2_rn(__expf(-c[6] * INV_LAM), __expf(-c[7] * INV_LAM));
        uint4 pk;
        pk.x = *(unsigned*)&h0; pk.y = *(unsigned*)&h1;
        pk.z = *(unsigned*)&h2; pk.w = *(unsigned*)&h3;
        *(uint4*)(g_E + row * N + bn + tx * 8) = pk;
    }
}

// ============================================================
// 3) init g = 0, Eg = 1
// ============================================================
__global__ void init_g() {
    int j = blockIdx.x * 256 + threadIdx.x;
    g_g[j] = 0.0f;
    g_Eg[j] = 1.0f;
}

// ============================================================
// 4) row pass: s_i = sum_j E_ij * Eg_j ;  f = -lam*logN - lam*log(s)
//    8 rows per block; Eg cached in regs (32 per thread)
// ============================================================
__global__ __launch_bounds__(256) void row_pass() {
    __shared__ float sEg[N];          // 32 KB
    __shared__ float swarp[8];
    const int tid = threadIdx.x;
    const int lane = tid & 31;
    const int wid = tid >> 5;

    for (int k = tid; k < N; k += 256) sEg[k] = g_Eg[k];
    __syncthreads();

    // each thread's 32 columns: cols = k*2048 + tid*8 + c
    float eg[4][8];
#pragma unroll
    for (int k = 0; k < 4; k++)
#pragma unroll
        for (int c = 0; c < 8; c++) eg[k][c] = sEg[k * 2048 + tid * 8 + c];

    const int i0 = blockIdx.x * ROWS_PER_BLK;

#pragma unroll 1
    for (int r = 0; r < ROWS_PER_BLK; r++) {
        const __half* __restrict__ row = g_E + (size_t)(i0 + r) * N;
        uint4 v[4];
#pragma unroll
        for (int k = 0; k < 4; k++)
            v[k] = *(const uint4*)(row + k * 2048 + tid * 8);

        float a0 = 0.0f, a1 = 0.0f;
#pragma unroll
        for (int k = 0; k < 4; k++) {
            const __half2* hp = (const __half2*)&v[k];
            float2 f0 = __half22float2(hp[0]);
            float2 f1 = __half22float2(hp[1]);
            float2 f2 = __half22float2(hp[2]);
            float2 f3 = __half22float2(hp[3]);
            a0 = fmaf(f0.x, eg[k][0], a0);
            a1 = fmaf(f0.y, eg[k][1], a1);
            a0 = fmaf(f1.x, eg[k][2], a0);
            a1 = fmaf(f1.y, eg[k][3], a1);
            a0 = fmaf(f2.x, eg[k][4], a0);
            a1 = fmaf(f2.y, eg[k][5], a1);
            a0 = fmaf(f3.x, eg[k][6], a0);
            a1 = fmaf(f3.y, eg[k][7], a1);
        }
        float acc = a0 + a1;
#pragma unroll
        for (int o = 16; o > 0; o >>= 1)
            acc += __shfl_down_sync(0xffffffffu, acc, o);
        if (lane == 0) swarp[wid] = acc;
        __syncthreads();
        if (tid == 0) {
            float s = swarp[0] + swarp[1] + swarp[2] + swarp[3]
                    + swarp[4] + swarp[5] + swarp[6] + swarp[7];
            float f = NEG_LAM_LOGN - LAMF * logf(s);
            g_f[i0 + r] = f;
            g_Ef[i0 + r] = __expf(f * INV_LAM);
        }
        __syncthreads();
    }
}

// ============================================================
// 5) column pass partial: s'_j(chunk) = sum_{i in chunk} E_ij * Ef_i
//    grid (N/2048, CCHUNK); thread handles 8 consecutive columns
// ============================================================
__global__ __launch_bounds__(256) void col_pass() {
    __shared__ float sEf[CROWS];
    const int tid = threadIdx.x;
    const int i0 = blockIdx.y * CROWS;
    if (tid < CROWS) sEf[tid] = g_Ef[i0 + tid];
    __syncthreads();

    const int j0 = blockIdx.x * 2048 + tid * 8;
    const __half* __restrict__ base = g_E + (size_t)i0 * N + j0;

    float acc[8];
#pragma unroll
    for (int c = 0; c < 8; c++) acc[c] = 0.0f;

#pragma unroll 1
    for (int r0 = 0; r0 < CROWS; r0 += 8) {
        uint4 v[8];
#pragma unroll
        for (int u = 0; u < 8; u++)
            v[u] = *(const uint4*)(base + (size_t)(r0 + u) * N);
#pragma unroll
        for (int u = 0; u < 8; u++) {
            float ef = sEf[r0 + u];
            const __half2* hp = (const __half2*)&v[u];
            float2 f0 = __half22float2(hp[0]);
            float2 f1 = __half22float2(hp[1]);
            float2 f2 = __half22float2(hp[2]);
            float2 f3 = __half22float2(hp[3]);
            acc[0] = fmaf(f0.x, ef, acc[0]);
            acc[1] = fmaf(f0.y, ef, acc[1]);
            acc[2] = fmaf(f1.x, ef, acc[2]);
            acc[3] = fmaf(f1.y, ef, acc[3]);
            acc[4] = fmaf(f2.x, ef, acc[4]);
            acc[5] = fmaf(f2.y, ef, acc[5]);
            acc[6] = fmaf(f3.x, ef, acc[6]);
            acc[7] = fmaf(f3.y, ef, acc[7]);
        }
    }
    float* p = g_part + (size_t)blockIdx.y * N + j0;
    *(float4*)&p[0] = make_float4(acc[0], acc[1], acc[2], acc[3]);
    *(float4*)&p[4] = make_float4(acc[4], acc[5], acc[6], acc[7]);
}

// ============================================================
// 6) column combine: g_j = -lam*logN - lam*log(sum of partials)
// ============================================================
__global__ __launch_bounds__(256) void col_combine() {
    const int j = blockIdx.x * 256 + threadIdx.x;
    float s = 0.0f;
#pragma unroll
    for (int c = 0; c < CCHUNK; c++) s += g_part[(size_t)c * N + j];
    float g = NEG_LAM_LOGN - LAMF * logf(s);
    g_g[j] = g;
    g_Eg[j] = __expf(g * INV_LAM);
}

// ============================================================
// 7) final: pi = exp((f_i + g_j - C)/lam) from fp32 C; row cost partials
//    NOTE: out+1 is only 4-byte aligned -> SCALAR stores for pi.
// ============================================================
__global__ __launch_bounds__(256) void pi_cost(float* __restrict__ out) {
    const int i = blockIdx.x;
    const int tid = threadIdx.x;
    const float fi = g_f[i];
    const float* __restrict__ Crow = g_C + (size_t)i * N;
    float* __restrict__ orow = out + 1 + (size_t)i * N;

    float acc = 0.0f;
#pragma unroll
    for (int k = 0; k < 8; k++) {
        int j = (k * 256 + tid) * 4;
        float4 C4 = *(const float4*)&Crow[j];
        float4 G4 = *(const float4*)&g_g[j];
        float px = __expf((fi + G4.x - C4.x) * INV_LAM);
        float py = __expf((fi + G4.y - C4.y) * INV_LAM);
        float pz = __expf((fi + G4.z - C4.z) * INV_LAM);
        float pw = __expf((fi + G4.w - C4.w) * INV_LAM);
        orow[j + 0] = px;
        orow[j + 1] = py;
        orow[j + 2] = pz;
        orow[j + 3] = pw;
        acc = fmaf(px, C4.x, acc);
        acc = fmaf(py, C4.y, acc);
        acc = fmaf(pz, C4.z, acc);
        acc = fmaf(pw, C4.w, acc);
    }
    __shared__ float sh[256];
    sh[tid] = acc;
    __syncthreads();
    for (int off = 128; off > 0; off >>= 1) {
        if (tid < off) sh[tid] += sh[tid + off];
        __syncthreads();
    }
    if (tid == 0) g_cost[i] = sh[0];
}

// ============================================================
// 8) deterministic final cost reduction
// ============================================================
__global__ __launch_bounds__(1024) void cost_reduce(float* __restrict__ out) {
    __shared__ float sh[1024];
    float a = 0.0f;
    for (int k = threadIdx.x; k < N; k += 1024) a += g_cost[k];
    sh[threadIdx.x] = a;
    __syncthreads();
    for (int off = 512; off > 0; off >>= 1) {
        if (threadIdx.x < off) sh[threadIdx.x] += sh[threadIdx.x + off];
        __syncthreads();
    }
    if (threadIdx.x == 0) out[0] = sh[0];
}

// ============================================================
extern "C" void kernel_launch(void* const* d_in, const int* in_sizes, int n_in,
                              void* d_out, int out_size) {
    const float* X = (const float*)d_in[0];
    const float* Y = (const float*)d_in[1];
    float* out = (float*)d_out;

    norms_kernel<<<2 * N, 256>>>(X, Y);
    cost_gemm<<<dim3(N / GBN, N / GBM), 256>>>(X, Y);
    init_g<<<N / 256, 256>>>();

    for (int it = 0; it < 50; it++) {
        row_pass<<<N / ROWS_PER_BLK, 256>>>();
        col_pass<<<dim3(N / 2048, CCHUNK), 256>>>();
        col_combine<<<N / 256, 256>>>();
    }

    pi_cost<<<N, 256>>>(out);
    cost_reduce<<<1, 1024>>>(out);
}

// round 4
// speedup vs baseline: 2.7622x; 1.2772x over previous
#include <cuda_runtime.h>
#include <cuda_fp16.h>
#include <math.h>

#define N 8192
#define D 256
#define LAMF 10.0f
#define INV_LAM 0.1f
#define NEG_LAM_LOGN (-90.109133472792885f)
#define INV_N 1.220703125e-4f     // 1/8192

#define FROWS 16
#define FBLOCKS (N / FROWS)       // 512 row-chunks / partials
#define P2 16                     // second-stage partial count

// ---- scratch (static device globals; no allocation allowed) ----
__device__ float  g_C[(size_t)N * N];   // fp32 cost matrix (final pass only)
__device__ __half g_E[(size_t)N * N];   // exp(-C/lam) fp16 (iteration passes)
__device__ float  g_f[N];
__device__ float  g_g[N];
__device__ float  g_s[N];               // row sums s_i
__device__ float  g_S[N];               // col sums S'_j
__device__ float  g_Eg[N];              // exp(g/lam) = (1/N)/S'
__device__ float  g_x2[N];
__device__ float  g_y2[N];
__device__ float  g_part[(size_t)FBLOCKS * N];   // 16 MB col partials
__device__ float  g_p2[(size_t)P2 * N];
__device__ float  g_cost[N];

// ============================================================
// 1) row norms of X and Y
// ============================================================
__global__ __launch_bounds__(256) void norms_kernel(const float* __restrict__ X,
                                                    const float* __restrict__ Y) {
    int r = blockIdx.x;
    const float* src = (r < N) ? (X + (size_t)r * D) : (Y + (size_t)(r - N) * D);
    float v = src[threadIdx.x];
    v *= v;
    __shared__ float sh[256];
    sh[threadIdx.x] = v;
    __syncthreads();
    for (int off = 128; off > 0; off >>= 1) {
        if (threadIdx.x < off) sh[threadIdx.x] += sh[threadIdx.x + off];
        __syncthreads();
    }
    if (threadIdx.x == 0) {
        if (r < N) g_x2[r] = sh[0];
        else       g_y2[r - N] = sh[0];
    }
}

// ============================================================
// 2) GEMM: C = sqrt(max(x2+y2-2XY^T,0)+1e-6), also E = exp(-C/lam) fp16
// ============================================================
#define GBM 128
#define GBN 128
#define GBK 16

__global__ __launch_bounds__(256) void cost_gemm(const float* __restrict__ X,
                                                 const float* __restrict__ Y) {
    __shared__ float Xs[GBK][GBM + 4];
    __shared__ float Ys[GBK][GBN + 4];

    const int tid = threadIdx.x;
    const int bm = blockIdx.y * GBM;
    const int bn = blockIdx.x * GBN;
    const int tx = tid & 15;
    const int ty = tid >> 4;
    const int lr = tid >> 2;
    const int lk = (tid & 3) * 4;

    float acc[8][8];
#pragma unroll
    for (int i = 0; i < 8; i++)
#pragma unroll
        for (int j = 0; j < 8; j++) acc[i][j] = 0.0f;

    for (int k0 = 0; k0 < D; k0 += GBK) {
#pragma unroll
        for (int h = 0; h < 2; h++) {
            int row = lr + h * 64;
            float4 v = *(const float4*)&X[(size_t)(bm + row) * D + k0 + lk];
            Xs[lk + 0][row] = v.x; Xs[lk + 1][row] = v.y;
            Xs[lk + 2][row] = v.z; Xs[lk + 3][row] = v.w;
            float4 w = *(const float4*)&Y[(size_t)(bn + row) * D + k0 + lk];
            Ys[lk + 0][row] = w.x; Ys[lk + 1][row] = w.y;
            Ys[lk + 2][row] = w.z; Ys[lk + 3][row] = w.w;
        }
        __syncthreads();

#pragma unroll
        for (int k = 0; k < GBK; k++) {
            float a[8], b[8];
            *(float4*)&a[0] = *(const float4*)&Xs[k][ty * 8];
            *(float4*)&a[4] = *(const float4*)&Xs[k][ty * 8 + 4];
            *(float4*)&b[0] = *(const float4*)&Ys[k][tx * 8];
            *(float4*)&b[4] = *(const float4*)&Ys[k][tx * 8 + 4];
#pragma unroll
            for (int i = 0; i < 8; i++)
#pragma unroll
                for (int j = 0; j < 8; j++) acc[i][j] = fmaf(a[i], b[j], acc[i][j]);
        }
        __syncthreads();
    }

    float x2[8], y2[8];
#pragma unroll
    for (int i = 0; i < 8; i++) x2[i] = g_x2[bm + ty * 8 + i];
#pragma unroll
    for (int j = 0; j < 8; j++) y2[j] = g_y2[bn + tx * 8 + j];

#pragma unroll
    for (int i = 0; i < 8; i++) {
        size_t row = (size_t)(bm + ty * 8 + i);
        float c[8];
#pragma unroll
        for (int j = 0; j < 8; j++) {
            float sq = x2[i] + y2[j] - 2.0f * acc[i][j];
            c[j] = sqrtf(fmaxf(sq, 0.0f) + 1e-6f);
        }
        float* crow = g_C + row * N + bn + tx * 8;
        *(float4*)&crow[0] = make_float4(c[0], c[1], c[2], c[3]);
        *(float4*)&crow[4] = make_float4(c[4], c[5], c[6], c[7]);

        __half2 h0 = __floats2half2_rn(__expf(-c[0] * INV_LAM), __expf(-c[1] * INV_LAM));
        __half2 h1 = __floats2half2_rn(__expf(-c[2] * INV_LAM), __expf(-c[3] * INV_LAM));
        __half2 h2 = __floats2half2_rn(__expf(-c[4] * INV_LAM), __expf(-c[5] * INV_LAM));
        __half2 h3 = __floats2half2_rn(__expf(-c[6] * INV_LAM), __expf(-c[7] * INV_LAM));
        uint4 pk;
        pk.x = *(unsigned*)&h0; pk.y = *(unsigned*)&h1;
        pk.z = *(unsigned*)&h2; pk.w = *(unsigned*)&h3;
        *(uint4*)(g_E + row * N + bn + tx * 8) = pk;
    }
}

// ============================================================
// 3) init Eg = 1
// ============================================================
__global__ void init_g() {
    int j = blockIdx.x * 256 + threadIdx.x;
    g_Eg[j] = 1.0f;
}

// ============================================================
// 4) FUSED pass: for each row i in chunk:
//      s_i = sum_j E_ij * Eg_j      (dot with smem Eg)
//      ef  = (1/N)/s_i              (no exp/log!)
//      acc_j += E_ij * ef           (reuse E regs)
//    then write per-chunk col partials.
//    512 blocks x 16 rows, 256 threads, 32 cols/thread, double-buffered rows.
// ============================================================
__global__ __launch_bounds__(256) void fused_pass() {
    __shared__ float sEg[N];          // 32 KB
    __shared__ float swarp[8];
    __shared__ float sEf;
    const int tid = threadIdx.x;
    const int lane = tid & 31;
    const int wid = tid >> 5;

    for (int k = tid; k < N; k += 256) sEg[k] = g_Eg[k];
    __syncthreads();

    float eg[4][8];
#pragma unroll
    for (int k = 0; k < 4; k++)
#pragma unroll
        for (int c = 0; c < 8; c++) eg[k][c] = sEg[k * 2048 + tid * 8 + c];

    const int i0 = blockIdx.x * FROWS;

    float acc[4][8];
#pragma unroll
    for (int k = 0; k < 4; k++)
#pragma unroll
        for (int c = 0; c < 8; c++) acc[k][c] = 0.0f;

    uint4 v[4];
    {
        const __half* __restrict__ row = g_E + (size_t)i0 * N;
#pragma unroll
        for (int k = 0; k < 4; k++)
            v[k] = *(const uint4*)(row + k * 2048 + tid * 8);
    }

#pragma unroll 1
    for (int r = 0; r < FROWS; r++) {
        // ---- dot with Eg ----
        float a0 = 0.0f, a1 = 0.0f;
#pragma unroll
        for (int k = 0; k < 4; k++) {
            const __half2* hp = (const __half2*)&v[k];
            float2 f0 = __half22float2(hp[0]);
            float2 f1 = __half22float2(hp[1]);
            float2 f2 = __half22float2(hp[2]);
            float2 f3 = __half22float2(hp[3]);
            a0 = fmaf(f0.x, eg[k][0], a0);
            a1 = fmaf(f0.y, eg[k][1], a1);
            a0 = fmaf(f1.x, eg[k][2], a0);
            a1 = fmaf(f1.y, eg[k][3], a1);
            a0 = fmaf(f2.x, eg[k][4], a0);
            a1 = fmaf(f2.y, eg[k][5], a1);
            a0 = fmaf(f3.x, eg[k][6], a0);
            a1 = fmaf(f3.y, eg[k][7], a1);
        }
        float p = a0 + a1;
#pragma unroll
        for (int o = 16; o > 0; o >>= 1)
            p += __shfl_down_sync(0xffffffffu, p, o);
        if (lane == 0) swarp[wid] = p;

        // ---- preload next row BEFORE the barrier (hide latency) ----
        uint4 vn[4];
        {
            int rn = (r + 1 < FROWS) ? (r + 1) : r;   // last iter: redundant reload (cached)
            const __half* __restrict__ rowp = g_E + (size_t)(i0 + rn) * N;
#pragma unroll
            for (int k = 0; k < 4; k++)
                vn[k] = *(const uint4*)(rowp + k * 2048 + tid * 8);
        }
        __syncthreads();
        if (tid == 0) {
            float s = swarp[0] + swarp[1] + swarp[2] + swarp[3]
                    + swarp[4] + swarp[5] + swarp[6] + swarp[7];
            g_s[i0 + r] = s;
            sEf = INV_N / s;
        }
        __syncthreads();
        const float ef = sEf;

        // ---- accumulate column partials with the SAME registers ----
#pragma unroll
        for (int k = 0; k < 4; k++) {
            const __half2* hp = (const __half2*)&v[k];
            float2 f0 = __half22float2(hp[0]);
            float2 f1 = __half22float2(hp[1]);
            float2 f2 = __half22float2(hp[2]);
            float2 f3 = __half22float2(hp[3]);
            acc[k][0] = fmaf(f0.x, ef, acc[k][0]);
            acc[k][1] = fmaf(f0.y, ef, acc[k][1]);
            acc[k][2] = fmaf(f1.x, ef, acc[k][2]);
            acc[k][3] = fmaf(f1.y, ef, acc[k][3]);
            acc[k][4] = fmaf(f2.x, ef, acc[k][4]);
            acc[k][5] = fmaf(f2.y, ef, acc[k][5]);
            acc[k][6] = fmaf(f3.x, ef, acc[k][6]);
            acc[k][7] = fmaf(f3.y, ef, acc[k][7]);
        }
#pragma unroll
        for (int k = 0; k < 4; k++) v[k] = vn[k];
    }

    float* part = g_part + (size_t)blockIdx.x * N;
#pragma unroll
    for (int k = 0; k < 4; k++) {
        *(float4*)&part[k * 2048 + tid * 8]     = make_float4(acc[k][0], acc[k][1], acc[k][2], acc[k][3]);
        *(float4*)&part[k * 2048 + tid * 8 + 4] = make_float4(acc[k][4], acc[k][5], acc[k][6], acc[k][7]);
    }
}

// ============================================================
// 5) combine stage 1: sum 32 of 512 partials -> g_p2[16][N]
// ============================================================
__global__ __launch_bounds__(256) void combine1() {
    const int j = blockIdx.x * 256 + threadIdx.x;
    const int c0 = blockIdx.y * (FBLOCKS / P2);
    float s = 0.0f;
#pragma unroll 8
    for (int c = 0; c < FBLOCKS / P2; c++)
        s += g_part[(size_t)(c0 + c) * N + j];
    g_p2[(size_t)blockIdx.y * N + j] = s;
}

// ============================================================
// 6) combine stage 2: S'_j, Eg = (1/N)/S'
// ============================================================
__global__ __launch_bounds__(256) void combine2() {
    const int j = blockIdx.x * 256 + threadIdx.x;
    float s = 0.0f;
#pragma unroll
    for (int c = 0; c < P2; c++) s += g_p2[(size_t)c * N + j];
    g_S[j] = s;
    g_Eg[j] = INV_N / s;
}

// ============================================================
// 7) finalize f, g (logs only here)
// ============================================================
__global__ __launch_bounds__(256) void final_fg() {
    const int i = blockIdx.x * 256 + threadIdx.x;
    g_f[i] = NEG_LAM_LOGN - LAMF * logf(g_s[i]);
    g_g[i] = NEG_LAM_LOGN - LAMF * logf(g_S[i]);
}

// ============================================================
// 8) final: pi = exp((f_i + g_j - C)/lam) from fp32 C; row cost partials
//    NOTE: out+1 is only 4-byte aligned -> SCALAR stores for pi.
// ============================================================
__global__ __launch_bounds__(256) void pi_cost(float* __restrict__ out) {
    const int i = blockIdx.x;
    const int tid = threadIdx.x;
    const float fi = g_f[i];
    const float* __restrict__ Crow = g_C + (size_t)i * N;
    float* __restrict__ orow = out + 1 + (size_t)i * N;

    float acc = 0.0f;
#pragma unroll
    for (int k = 0; k < 8; k++) {
        int j = (k * 256 + tid) * 4;
        float4 C4 = *(const float4*)&Crow[j];
        float4 G4 = *(const float4*)&g_g[j];
        float px = __expf((fi + G4.x - C4.x) * INV_LAM);
        float py = __expf((fi + G4.y - C4.y) * INV_LAM);
        float pz = __expf((fi + G4.z - C4.z) * INV_LAM);
        float pw = __expf((fi + G4.w - C4.w) * INV_LAM);
        orow[j + 0] = px;
        orow[j + 1] = py;
        orow[j + 2] = pz;
        orow[j + 3] = pw;
        acc = fmaf(px, C4.x, acc);
        acc = fmaf(py, C4.y, acc);
        acc = fmaf(pz, C4.z, acc);
        acc = fmaf(pw, C4.w, acc);
    }
    __shared__ float sh[256];
    sh[tid] = acc;
    __syncthreads();
    for (int off = 128; off > 0; off >>= 1) {
        if (tid < off) sh[tid] += sh[tid + off];
        __syncthreads();
    }
    if (tid == 0) g_cost[i] = sh[0];
}

// ============================================================
// 9) deterministic final cost reduction
// ============================================================
__global__ __launch_bounds__(1024) void cost_reduce(float* __restrict__ out) {
    __shared__ float sh[1024];
    float a = 0.0f;
    for (int k = threadIdx.x; k < N; k += 1024) a += g_cost[k];
    sh[threadIdx.x] = a;
    __syncthreads();
    for (int off = 512; off > 0; off >>= 1) {
        if (threadIdx.x < off) sh[threadIdx.x] += sh[threadIdx.x + off];
        __syncthreads();
    }
    if (threadIdx.x == 0) out[0] = sh[0];
}

// ============================================================
extern "C" void kernel_launch(void* const* d_in, const int* in_sizes, int n_in,
                              void* d_out, int out_size) {
    const float* X = (const float*)d_in[0];
    const float* Y = (const float*)d_in[1];
    float* out = (float*)d_out;

    norms_kernel<<<2 * N, 256>>>(X, Y);
    cost_gemm<<<dim3(N / GBN, N / GBM), 256>>>(X, Y);
    init_g<<<N / 256, 256>>>();

    for (int it = 0; it < 50; it++) {
        fused_pass<<<FBLOCKS, 256>>>();
        combine1<<<dim3(N / 256, P2), 256>>>();
        combine2<<<N / 256, 256>>>();
    }

    final_fg<<<N / 256, 256>>>();
    pi_cost<<<N, 256>>>(out);
    cost_reduce<<<1, 1024>>>(out);
}